// round 5
// baseline (speedup 1.0000x reference)
#include <cuda_runtime.h>
#include <cstdint>

// GroupQuantizedLinear: y = (round(clip(W,-8,7)) * scale_per_group) @ x
// W: [8192, 8192] f32, scales: [8192, 64] f32 (group size 128), x: [8192] f32
// HBM-bound GEMV over 256 MB. Persistent blocks + atomic work counter to
// eliminate wave quantization; 4 rows interleaved per quad for high MLP.

static constexpr int IN_DIM  = 8192;
static constexpr int OUT_DIM = 8192;
static constexpr int GROUPS  = 64;       // group size = 128 channels = 32 float4
static constexpr int THREADS = 256;
static constexpr int ROWS    = 4;        // rows per work quad
static constexpr int VEC4    = IN_DIM / 4;        // 2048 float4 per row
static constexpr int ITERS   = VEC4 / THREADS;    // 8 float4 loads/thread/row
static constexpr int NWARP   = THREADS / 32;      // 8
static constexpr int NQUAD   = OUT_DIM / ROWS;    // 2048 work items
static constexpr int NBLOCKS = 148 * 4;           // resident capacity (persistent)

__device__ unsigned g_quad_counter;

__global__ void gql_reset_kernel() { g_quad_counter = 0u; }

__device__ __forceinline__ float qdot(float4 wv, float4 xv) {
    const float q0 = rintf(fminf(fmaxf(wv.x, -8.0f), 7.0f));
    const float q1 = rintf(fminf(fmaxf(wv.y, -8.0f), 7.0f));
    const float q2 = rintf(fminf(fmaxf(wv.z, -8.0f), 7.0f));
    const float q3 = rintf(fminf(fmaxf(wv.w, -8.0f), 7.0f));
    return q0 * xv.x + q1 * xv.y + q2 * xv.z + q3 * xv.w;
}

__global__ __launch_bounds__(THREADS, 4)
void gql_kernel(const float* __restrict__ x,
                const float* __restrict__ w,
                const float* __restrict__ scales,
                float* __restrict__ out)
{
    __shared__ float4   xs[VEC4];            // 32 KB: x staged ONCE per block
    __shared__ float    red[ROWS][NWARP];    // per-warp partials
    __shared__ unsigned sQuad;

    const int t    = threadIdx.x;
    const int wid  = t >> 5, lane = t & 31;

    // Stage x once (coalesced float4); reused across all quads this block takes.
    const float4* x4 = reinterpret_cast<const float4*>(x);
    #pragma unroll
    for (int i = t; i < VEC4; i += THREADS) xs[i] = x4[i];

    while (true) {
        if (t == 0) sQuad = atomicAdd(&g_quad_counter, 1u);
        __syncthreads();                     // publish sQuad (+ covers x staging 1st iter)
        const unsigned q = sQuad;
        if (q >= NQUAD) break;

        const int row0 = (int)q * ROWS;
        const float4* w0 = reinterpret_cast<const float4*>(w + (size_t)(row0 + 0) * IN_DIM);
        const float4* w1 = reinterpret_cast<const float4*>(w + (size_t)(row0 + 1) * IN_DIM);
        const float4* w2 = reinterpret_cast<const float4*>(w + (size_t)(row0 + 2) * IN_DIM);
        const float4* w3 = reinterpret_cast<const float4*>(w + (size_t)(row0 + 3) * IN_DIM);
        const float* s0 = scales + (size_t)(row0 + 0) * GROUPS;
        const float* s1 = scales + (size_t)(row0 + 1) * GROUPS;
        const float* s2 = scales + (size_t)(row0 + 2) * GROUPS;
        const float* s3 = scales + (size_t)(row0 + 3) * GROUPS;

        float acc0 = 0.0f, acc1 = 0.0f, acc2 = 0.0f, acc3 = 0.0f;

        #pragma unroll
        for (int it = 0; it < ITERS; it++) {
            const int i4 = t + it * THREADS;     // float4 index within row
            // 4 independent streaming loads — high MLP, one xv reuse
            const float4 wv0 = __ldcs(w0 + i4);
            const float4 wv1 = __ldcs(w1 + i4);
            const float4 wv2 = __ldcs(w2 + i4);
            const float4 wv3 = __ldcs(w3 + i4);
            const float4 xv  = xs[i4];
            const int    g   = i4 >> 5;          // group = (4*i4)/128 (L1 hits)

            acc0 += __ldg(s0 + g) * qdot(wv0, xv);
            acc1 += __ldg(s1 + g) * qdot(wv1, xv);
            acc2 += __ldg(s2 + g) * qdot(wv2, xv);
            acc3 += __ldg(s3 + g) * qdot(wv3, xv);
        }

        // Warp-level reduction of all 4 accumulators
        #pragma unroll
        for (int off = 16; off; off >>= 1) {
            acc0 += __shfl_xor_sync(0xFFFFFFFFu, acc0, off);
            acc1 += __shfl_xor_sync(0xFFFFFFFFu, acc1, off);
            acc2 += __shfl_xor_sync(0xFFFFFFFFu, acc2, off);
            acc3 += __shfl_xor_sync(0xFFFFFFFFu, acc3, off);
        }
        if (lane == 0) {
            red[0][wid] = acc0;
            red[1][wid] = acc1;
            red[2][wid] = acc2;
            red[3][wid] = acc3;
        }
        __syncthreads();                     // publish red

        // Warps 0..3 each reduce one row's NWARP partials; all 32 lanes active.
        if (wid < ROWS) {
            float v = (lane < NWARP) ? red[wid][lane] : 0.0f;
            #pragma unroll
            for (int off = NWARP / 2; off; off >>= 1)
                v += __shfl_xor_sync(0xFFFFFFFFu, v, off);
            if (lane == 0) out[row0 + wid] = v;
        }
        __syncthreads();                     // protect red + sQuad before reuse
    }
}

extern "C" void kernel_launch(void* const* d_in, const int* in_sizes, int n_in,
                              void* d_out, int out_size)
{
    const float* x      = (const float*)d_in[0];   // [8192]
    const float* w      = (const float*)d_in[1];   // [8192*8192]
    const float* scales = (const float*)d_in[2];   // [8192*64]
    float* out = (float*)d_out;                    // [8192]

    gql_reset_kernel<<<1, 1>>>();
    gql_kernel<<<NBLOCKS, THREADS>>>(x, w, scales, out);
}